// round 4
// baseline (speedup 1.0000x reference)
#include <cuda_runtime.h>
#include <cstdint>

// Problem constants
#define B_TOTAL   32768
#define T_STEPS   28
#define IN_DIM    28
#define HIDDEN    128
#define GATES     512          // 4*HIDDEN, gate order i, j, f, o
#define KDIM      156          // IN_DIM + HIDDEN
#define LABELS    10
#define FORGET_BIAS 1.0f

// Tiling
#define BTILE     64           // batch rows per CTA
#define NTHREADS  512          // 8 row-groups x 64 col-groups
#define KT        26           // K tile (156 = 6*26)

// Shared memory strides (floats)
#define A_S       130          // duplicated A row: 2*BTILE + 2 pad (8B-aligned rows)
#define W_S       516          // GATES + 4 pad
#define C_S       130          // c pairs, width 128 + 2 pad

#define SMEM_FLOATS (KDIM*A_S + KT*W_S + BTILE*C_S)
#define SMEM_BYTES  (SMEM_FLOATS * 4)

typedef unsigned long long ull;

#define FMA_F32X2(d, a, b, c) \
    asm("fma.rn.f32x2 %0, %1, %2, %3;" : "=l"(d) : "l"(a), "l"(b), "l"(c))
#define PACK2(v, lo, hi) \
    asm("mov.b64 %0, {%1, %2};" : "=l"(v) : "f"(lo), "f"(hi))
#define UNPACK2(lo, hi, v) \
    asm("mov.b64 {%0, %1}, %2;" : "=f"(lo), "=f"(hi) : "l"(v))

__device__ __forceinline__ float sigf(float x) {
    return 1.0f / (1.0f + __expf(-x));
}
__device__ __forceinline__ float tanhf_fast(float x) {
    // 2*sigmoid(2x)-1 : saturates correctly at +-1, no overflow/NaN
    return 2.0f / (1.0f + __expf(-2.0f * x)) - 1.0f;
}

__global__ void __launch_bounds__(NTHREADS, 1)
lstm_kernel(const float* __restrict__ x,
            const float* __restrict__ W_lstm,
            const float* __restrict__ b_lstm,
            const float* __restrict__ W_fc,
            const float* __restrict__ b_fc,
            float* __restrict__ out)
{
    extern __shared__ float smem[];
    float* Adup = smem;                       // [KDIM][A_S]  A[k][2r]=A[k][2r+1]=a(k,r)
    float* Wt   = smem + KDIM * A_S;          // [KT][W_S]
    float* Csm  = Wt + KT * W_S;              // [BTILE][C_S] c state, paired (hu,hu+1)

    const int tid    = threadIdx.x;
    const int colgrp = tid & 63;              // 0..63 -> hidden-unit pair
    const int rowgrp = tid >> 6;              // 0..7
    const int r0     = rowgrp * 8;
    const int hu0    = colgrp * 2;
    const int b0     = blockIdx.x * BTILE;

    // ---- init: zero h rows of Adup and c state ----
    for (int idx = tid; idx < HIDDEN * (2 * BTILE); idx += NTHREADS) {
        int j = idx >> 7;                     // /128
        int r2 = idx & 127;
        Adup[(IN_DIM + j) * A_S + r2] = 0.0f;
    }
    for (int idx = tid; idx < BTILE * HIDDEN; idx += NTHREADS) {
        int r = idx >> 7;
        int cidx = idx & 127;
        Csm[r * C_S + cidx] = 0.0f;
    }

    // ---- per-thread constant: packed gate biases (cols hu0, hu0+1 of each gate) ----
    ull bias2[4];
#pragma unroll
    for (int g = 0; g < 4; ++g) {
        float2 bv = *(const float2*)&b_lstm[g * HIDDEN + hu0];
        PACK2(bias2[g], bv.x, bv.y);
    }

    for (int t = 0; t < T_STEPS; ++t) {
        // ---- stage x_t into Adup rows 0..27 (duplicated) ----
        for (int idx = tid; idx < BTILE * IN_DIM; idx += NTHREADS) {
            int r = idx / IN_DIM;
            int ci = idx - r * IN_DIM;
            float v = x[(size_t)(b0 + r) * (T_STEPS * IN_DIM) + t * IN_DIM + ci];
            *(float2*)&Adup[ci * A_S + 2 * r] = make_float2(v, v);
        }
        __syncthreads();   // x + h(prev step) + c visible; Wt free

        // ---- gates = [x|h] @ W + b,  64x512 tile, acc pairs (hu0,hu0+1) per gate ----
        ull acc2[8][4];
#pragma unroll
        for (int r = 0; r < 8; ++r)
#pragma unroll
            for (int g = 0; g < 4; ++g)
                acc2[r][g] = bias2[g];

        for (int kt = 0; kt < KDIM; kt += KT) {
            // stage W rows kt..kt+KT-1 (L2-resident)
            for (int idx = tid; idx < KT * GATES / 4; idx += NTHREADS) {
                int kk = idx >> 7;               // /(GATES/4)
                int cc = (idx & 127) << 2;
                float4 w4 = *(const float4*)&W_lstm[(kt + kk) * GATES + cc];
                *(float4*)&Wt[kk * W_S + cc] = w4;
            }
            __syncthreads();

            // A panel rows for THIS K-tile (fix: advance by kt)
            const float* Apan = Adup + kt * A_S + 2 * r0;

#pragma unroll 2
            for (int k = 0; k < KT; ++k) {
                ull wp[4];
#pragma unroll
                for (int g = 0; g < 4; ++g)
                    wp[g] = *(const ull*)&Wt[k * W_S + g * HIDDEN + hu0];
#pragma unroll
                for (int r = 0; r < 8; ++r) {
                    ull ap = *(const ull*)&Apan[k * A_S + 2 * r]; // broadcast LDS.64
#pragma unroll
                    for (int g = 0; g < 4; ++g)
                        FMA_F32X2(acc2[r][g], ap, wp[g], acc2[r][g]);
                }
            }
            __syncthreads();  // before Wt is overwritten by next tile
        }

        // ---- pointwise LSTM cell update (register/smem-local) ----
#pragma unroll
        for (int r = 0; r < 8; ++r) {
            int row = r0 + r;
            float ig0, ig1, jg0, jg1, fg0, fg1, og0, og1;
            UNPACK2(ig0, ig1, acc2[r][0]);
            UNPACK2(jg0, jg1, acc2[r][1]);
            UNPACK2(fg0, fg1, acc2[r][2]);
            UNPACK2(og0, og1, acc2[r][3]);

            ull cp = *(ull*)&Csm[row * C_S + hu0];
            float c0, c1;
            UNPACK2(c0, c1, cp);

            c0 = c0 * sigf(fg0 + FORGET_BIAS) + sigf(ig0) * tanhf_fast(jg0);
            c1 = c1 * sigf(fg1 + FORGET_BIAS) + sigf(ig1) * tanhf_fast(jg1);
            float h0 = tanhf_fast(c0) * sigf(og0);
            float h1 = tanhf_fast(c1) * sigf(og1);

            PACK2(cp, c0, c1);
            *(ull*)&Csm[row * C_S + hu0] = cp;

            // store h duplicated into A for next step's GEMM
            *(float2*)&Adup[(IN_DIM + hu0)     * A_S + 2 * row] = make_float2(h0, h0);
            *(float2*)&Adup[(IN_DIM + hu0 + 1) * A_S + 2 * row] = make_float2(h1, h1);
        }
        // No barrier needed here: h-writes are ordered before next step's GEMM
        // reads by the barrier that follows the x-staging loop.
    }

    __syncthreads();  // all final h visible

    // ---- logits = h @ W_fc + b_fc  (tiny: 64x10, K=128) ----
    for (int idx = tid; idx < BTILE * LABELS; idx += NTHREADS) {
        int r = idx / LABELS;
        int lab = idx - r * LABELS;
        float s = b_fc[lab];
#pragma unroll 4
        for (int k = 0; k < HIDDEN; ++k)
            s += Adup[(IN_DIM + k) * A_S + 2 * r] * W_fc[k * LABELS + lab];
        out[(size_t)(b0 + r) * LABELS + lab] = s;
    }
}

extern "C" void kernel_launch(void* const* d_in, const int* in_sizes, int n_in,
                              void* d_out, int out_size)
{
    const float* x      = (const float*)d_in[0];   // [32768, 28, 28]
    const float* W_lstm = (const float*)d_in[1];   // [156, 512]
    const float* b_lstm = (const float*)d_in[2];   // [512]
    const float* W_fc   = (const float*)d_in[3];   // [128, 10]
    const float* b_fc   = (const float*)d_in[4];   // [10]
    float* out          = (float*)d_out;           // [32768, 10]

    cudaFuncSetAttribute(lstm_kernel,
                         cudaFuncAttributeMaxDynamicSharedMemorySize, SMEM_BYTES);

    dim3 grid(B_TOTAL / BTILE);                    // 512 CTAs
    lstm_kernel<<<grid, NTHREADS, SMEM_BYTES>>>(x, W_lstm, b_lstm, W_fc, b_fc, out);
}

// round 5
// speedup vs baseline: 1.0031x; 1.0031x over previous
#include <cuda_runtime.h>
#include <cstdint>

// Problem constants
#define B_TOTAL   32768
#define T_STEPS   28
#define IN_DIM    28
#define HIDDEN    128
#define GATES     512          // 4*HIDDEN, gate order i, j, f, o
#define KDIM      156          // IN_DIM + HIDDEN
#define LABELS    10
#define FORGET_BIAS 1.0f

// Tiling
#define BTILE     64           // batch rows per CTA
#define NTHREADS  512          // 8 row-groups x 64 col-groups
#define KT        26           // K tile (156 = 6*26)

// Shared memory strides (floats)
#define A_S       130          // duplicated A row: 2*BTILE + 2 pad (8B-aligned rows)
#define W_S       516          // GATES + 4 pad
#define C_S       130          // c pairs, width 128 + 2 pad

#define SMEM_FLOATS (KDIM*A_S + KT*W_S + BTILE*C_S)
#define SMEM_BYTES  (SMEM_FLOATS * 4)

typedef unsigned long long ull;

#define FMA_F32X2(d, a, b, c) \
    asm("fma.rn.f32x2 %0, %1, %2, %3;" : "=l"(d) : "l"(a), "l"(b), "l"(c))
#define PACK2(v, lo, hi) \
    asm("mov.b64 %0, {%1, %2};" : "=l"(v) : "f"(lo), "f"(hi))
#define UNPACK2(lo, hi, v) \
    asm("mov.b64 {%0, %1}, %2;" : "=f"(lo), "=f"(hi) : "l"(v))

__device__ __forceinline__ float sigf(float x) {
    return 1.0f / (1.0f + __expf(-x));
}
__device__ __forceinline__ float tanhf_fast(float x) {
    // 2*sigmoid(2x)-1 : saturates correctly at +-1, no overflow/NaN
    return 2.0f / (1.0f + __expf(-2.0f * x)) - 1.0f;
}

__global__ void __launch_bounds__(NTHREADS, 1)
lstm_kernel(const float* __restrict__ x,
            const float* __restrict__ W_lstm,
            const float* __restrict__ b_lstm,
            const float* __restrict__ W_fc,
            const float* __restrict__ b_fc,
            float* __restrict__ out)
{
    extern __shared__ float smem[];
    float* Adup = smem;                       // [KDIM][A_S]  A[k][2r]=A[k][2r+1]=a(k,r)
    float* Wt   = smem + KDIM * A_S;          // [KT][W_S]
    float* Csm  = Wt + KT * W_S;              // [BTILE][C_S] c state, paired (hu,hu+1)

    const int tid    = threadIdx.x;
    const int colgrp = tid & 63;              // 0..63 -> hidden-unit pair
    const int rowgrp = tid >> 6;              // 0..7
    const int r0     = rowgrp * 8;
    const int hu0    = colgrp * 2;
    const int b0     = blockIdx.x * BTILE;

    // ---- init: zero h rows of Adup and c state ----
    for (int idx = tid; idx < HIDDEN * (2 * BTILE); idx += NTHREADS) {
        int j = idx >> 7;                     // /128
        int r2 = idx & 127;
        Adup[(IN_DIM + j) * A_S + r2] = 0.0f;
    }
    for (int idx = tid; idx < BTILE * HIDDEN; idx += NTHREADS) {
        int r = idx >> 7;
        int cidx = idx & 127;
        Csm[r * C_S + cidx] = 0.0f;
    }

    // ---- per-thread constant: packed gate biases (cols hu0, hu0+1 of each gate) ----
    ull bias2[4];
#pragma unroll
    for (int g = 0; g < 4; ++g) {
        float2 bv = *(const float2*)&b_lstm[g * HIDDEN + hu0];
        PACK2(bias2[g], bv.x, bv.y);
    }

    for (int t = 0; t < T_STEPS; ++t) {
        // ---- stage x_t into Adup rows 0..27 (duplicated) ----
        for (int idx = tid; idx < BTILE * IN_DIM; idx += NTHREADS) {
            int r = idx / IN_DIM;
            int ci = idx - r * IN_DIM;
            float v = x[(size_t)(b0 + r) * (T_STEPS * IN_DIM) + t * IN_DIM + ci];
            *(float2*)&Adup[ci * A_S + 2 * r] = make_float2(v, v);
        }
        __syncthreads();   // x + h(prev step) + c visible; Wt free

        // ---- gates = [x|h] @ W + b,  64x512 tile, acc pairs (hu0,hu0+1) per gate ----
        ull acc2[8][4];
#pragma unroll
        for (int r = 0; r < 8; ++r)
#pragma unroll
            for (int g = 0; g < 4; ++g)
                acc2[r][g] = bias2[g];

        for (int kt = 0; kt < KDIM; kt += KT) {
            // stage W rows kt..kt+KT-1 (L2-resident)
            for (int idx = tid; idx < KT * GATES / 4; idx += NTHREADS) {
                int kk = idx >> 7;               // /(GATES/4)
                int cc = (idx & 127) << 2;
                float4 w4 = *(const float4*)&W_lstm[(kt + kk) * GATES + cc];
                *(float4*)&Wt[kk * W_S + cc] = w4;
            }
            __syncthreads();

            // A panel rows for THIS K-tile (fix: advance by kt)
            const float* Apan = Adup + kt * A_S + 2 * r0;

#pragma unroll 2
            for (int k = 0; k < KT; ++k) {
                ull wp[4];
#pragma unroll
                for (int g = 0; g < 4; ++g)
                    wp[g] = *(const ull*)&Wt[k * W_S + g * HIDDEN + hu0];
#pragma unroll
                for (int r = 0; r < 8; ++r) {
                    ull ap = *(const ull*)&Apan[k * A_S + 2 * r]; // broadcast LDS.64
#pragma unroll
                    for (int g = 0; g < 4; ++g)
                        FMA_F32X2(acc2[r][g], ap, wp[g], acc2[r][g]);
                }
            }
            __syncthreads();  // before Wt is overwritten by next tile
        }

        // ---- pointwise LSTM cell update (register/smem-local) ----
#pragma unroll
        for (int r = 0; r < 8; ++r) {
            int row = r0 + r;
            float ig0, ig1, jg0, jg1, fg0, fg1, og0, og1;
            UNPACK2(ig0, ig1, acc2[r][0]);
            UNPACK2(jg0, jg1, acc2[r][1]);
            UNPACK2(fg0, fg1, acc2[r][2]);
            UNPACK2(og0, og1, acc2[r][3]);

            ull cp = *(ull*)&Csm[row * C_S + hu0];
            float c0, c1;
            UNPACK2(c0, c1, cp);

            c0 = c0 * sigf(fg0 + FORGET_BIAS) + sigf(ig0) * tanhf_fast(jg0);
            c1 = c1 * sigf(fg1 + FORGET_BIAS) + sigf(ig1) * tanhf_fast(jg1);
            float h0 = tanhf_fast(c0) * sigf(og0);
            float h1 = tanhf_fast(c1) * sigf(og1);

            PACK2(cp, c0, c1);
            *(ull*)&Csm[row * C_S + hu0] = cp;

            // store h duplicated into A for next step's GEMM
            *(float2*)&Adup[(IN_DIM + hu0)     * A_S + 2 * row] = make_float2(h0, h0);
            *(float2*)&Adup[(IN_DIM + hu0 + 1) * A_S + 2 * row] = make_float2(h1, h1);
        }
        // No barrier needed here: h-writes are ordered before next step's GEMM
        // reads by the barrier that follows the x-staging loop.
    }

    __syncthreads();  // all final h visible

    // ---- logits = h @ W_fc + b_fc  (tiny: 64x10, K=128) ----
    for (int idx = tid; idx < BTILE * LABELS; idx += NTHREADS) {
        int r = idx / LABELS;
        int lab = idx - r * LABELS;
        float s = b_fc[lab];
#pragma unroll 4
        for (int k = 0; k < HIDDEN; ++k)
            s += Adup[(IN_DIM + k) * A_S + 2 * r] * W_fc[k * LABELS + lab];
        out[(size_t)(b0 + r) * LABELS + lab] = s;
    }
}

extern "C" void kernel_launch(void* const* d_in, const int* in_sizes, int n_in,
                              void* d_out, int out_size)
{
    const float* x      = (const float*)d_in[0];   // [32768, 28, 28]
    const float* W_lstm = (const float*)d_in[1];   // [156, 512]
    const float* b_lstm = (const float*)d_in[2];   // [512]
    const float* W_fc   = (const float*)d_in[3];   // [128, 10]
    const float* b_fc   = (const float*)d_in[4];   // [10]
    float* out          = (float*)d_out;           // [32768, 10]

    cudaFuncSetAttribute(lstm_kernel,
                         cudaFuncAttributeMaxDynamicSharedMemorySize, SMEM_BYTES);

    dim3 grid(B_TOTAL / BTILE);                    // 512 CTAs
    lstm_kernel<<<grid, NTHREADS, SMEM_BYTES>>>(x, W_lstm, b_lstm, W_fc, b_fc, out);
}

// round 9
// speedup vs baseline: 2.7038x; 2.6954x over previous
#include <cuda_runtime.h>
#include <cuda_fp16.h>
#include <cstdint>

#define T_STEPS 28
#define LABELS  10
#define MTILE   64
#define NTHR    256
#define AST     168                      // half stride (336B: odd multiple of 16B -> conflict-free ldmatrix)
#define SM_A    (512*AST)                // A starts after W' (in halfs)
#define SMEM_TOTAL ((512*AST + 64*AST)*2)   // 193536 B

__device__ __forceinline__ uint32_t smem_u32(const void* p){
    uint32_t a; asm("{ .reg .u64 t; cvta.to.shared.u64 t, %1; cvt.u32.u64 %0, t; }":"=r"(a):"l"(p)); return a;
}
__device__ __forceinline__ uint32_t h2u(__half2 v){ return *reinterpret_cast<uint32_t*>(&v); }

__device__ __forceinline__ float sigf(float x){ return 1.0f/(1.0f+__expf(-x)); }
__device__ __forceinline__ float tanhff(float x){ return 2.0f/(1.0f+__expf(-2.0f*x))-1.0f; }

#define LDSM4(r,a) asm volatile("ldmatrix.sync.aligned.m8n8.x4.shared.b16 {%0,%1,%2,%3},[%4];" \
    :"=r"((r)[0]),"=r"((r)[1]),"=r"((r)[2]),"=r"((r)[3]):"r"(a))
#define LDSM2(r,a) asm volatile("ldmatrix.sync.aligned.m8n8.x2.shared.b16 {%0,%1},[%2];" \
    :"=r"((r)[0]),"=r"((r)[1]):"r"(a))
#define MMA16816(c,a,b) asm volatile( \
    "mma.sync.aligned.m16n8k16.row.col.f32.f16.f16.f32 {%0,%1,%2,%3},{%4,%5,%6,%7},{%8,%9},{%0,%1,%2,%3};" \
    :"+f"((c)[0]),"+f"((c)[1]),"+f"((c)[2]),"+f"((c)[3]) \
    :"r"((a)[0]),"r"((a)[1]),"r"((a)[2]),"r"((a)[3]),"r"((b)[0]),"r"((b)[1]))

__global__ void __launch_bounds__(NTHR)
lstm_mma(const float* __restrict__ x, const float* __restrict__ W_lstm,
         const float* __restrict__ b_lstm, const float* __restrict__ W_fc,
         const float* __restrict__ b_fc, float* __restrict__ out)
{
    extern __shared__ __align__(16) __half sm[];
    __half* Wst = sm;            // [512 n'][AST k]  k-contiguous per column
    __half* Ast = sm + SM_A;     // [64 r][AST k]

    const int tid  = threadIdx.x;
    const int wid  = tid >> 5;
    const int lane = tid & 31;
    const int wm   = wid >> 2;          // 0..1 : rows 32*wm
    const int wn   = wid & 3;           // 0..3 : 64 cols per chunk-slice
    const int gid  = lane >> 2;
    const int tig  = lane & 3;
    const int b0   = blockIdx.x * MTILE;

    // ---- stage W' once: k-map {0..27:x-rows, 28:bias, 29..31:0, 32..159:h-rows},
    //      column interleave n' = 4*hu + g  (g: 0=i,1=j,2=f,3=o; orig col = g*128+hu) ----
    for (int idx = tid; idx < 512*160; idx += NTHR) {
        int k = idx >> 9, col = idx & 511;
        float v = 0.0f;
        if (k < 28)       v = W_lstm[k*512 + col];
        else if (k == 28) v = b_lstm[col];
        else if (k >= 32) v = W_lstm[(k-4)*512 + col];
        int np = ((col & 127) << 2) | (col >> 7);      // 4*hu + g
        Wst[np*AST + k] = __float2half_rn(v);
    }
    // ---- A static region: bias=1 at k=28, zeros k=29..159 (h starts zero) ----
    for (int idx = tid; idx < 64*132; idx += NTHR) {
        int r = idx / 132, k = 28 + idx % 132;
        Ast[r*AST + k] = __float2half_rn(k == 28 ? 1.0f : 0.0f);
    }

    const uint32_t abase = smem_u32(Ast);
    const uint32_t wbase = smem_u32(Wst);
    // lane-fixed ldmatrix address components
    const uint32_t a_lane = (uint32_t)((lane & 15) * AST + (lane >> 4) * 8) * 2;
    const uint32_t b_lane = (uint32_t)((lane & 7) * AST + ((lane >> 3) & 1) * 8) * 2;

    float cst[2][16], hp[2][16];
#pragma unroll
    for (int i = 0; i < 16; ++i) { cst[0][i] = 0.f; cst[1][i] = 0.f; }

    const bool odd = (tig & 1);

    for (int t = 0; t < T_STEPS; ++t) {
        // ---- stage x_t fp16 into A cols 0..27 ----
        for (int idx = tid; idx < 64*7; idx += NTHR) {
            int r = idx / 7, q = idx - r*7;
            float4 v = *(const float4*)(x + (size_t)(b0 + r)*784 + t*28 + q*4);
            uint2 pk;
            pk.x = h2u(__floats2half2_rn(v.x, v.y));
            pk.y = h2u(__floats2half2_rn(v.z, v.w));
            *(uint2*)(Ast + r*AST + 4*q) = pk;
        }
        __syncthreads();   // x + h(t-1) + W' visible to all

#pragma unroll
        for (int ch = 0; ch < 2; ++ch) {
            float acc[2][8][4];
#pragma unroll
            for (int nt = 0; nt < 8; ++nt)
#pragma unroll
                for (int e = 0; e < 4; ++e) { acc[0][nt][e] = 0.f; acc[1][nt][e] = 0.f; }

            // ---- GEMM: rows 32wm..+31, cols n' = 256ch+64wn .. +63, K=160 ----
#pragma unroll
            for (int kt = 0; kt < 10; ++kt) {
                uint32_t a0[4], a1[4];
                uint32_t aaddr = abase + (uint32_t)(wm*32*AST + kt*16)*2 + a_lane;
                LDSM4(a0, aaddr);
                LDSM4(a1, aaddr + 16*AST*2);
#pragma unroll
                for (int nt = 0; nt < 8; ++nt) {
                    uint32_t b[2];
                    uint32_t baddr = wbase + (uint32_t)(((ch*256 + wn*64 + nt*8)*AST) + kt*16)*2 + b_lane;
                    LDSM2(b, baddr);
                    MMA16816(acc[0][nt], a0, b);
                    MMA16816(acc[1][nt], a1, b);
                }
            }

            // ---- epilogue: lane-pair exchange -> uniform cell update ----
#pragma unroll
            for (int mt = 0; mt < 2; ++mt)
#pragma unroll
            for (int nt = 0; nt < 8; ++nt) {
                float c0 = acc[mt][nt][0], c1 = acc[mt][nt][1];
                float c2 = acc[mt][nt][2], c3 = acc[mt][nt][3];
                // even lane owns (i,j)@rows{g,g+8}; odd owns (f,o)@rows{g,g+8}
                float s0 = odd ? c0 : c2;            // send: odd->its (f,o)@r_a ; even->its (i,j)@r_b
                float s1 = odd ? c1 : c3;
                float r0 = __shfl_sync(0xffffffffu, s0, lane ^ 1);
                float r1 = __shfl_sync(0xffffffffu, s1, lane ^ 1);
                float gi = odd ? r0 : c0;
                float gj = odd ? r1 : c1;
                float gf = odd ? c2 : r0;
                float go = odd ? c3 : r1;
                int ii = mt*8 + nt;
                float cs = cst[ch][ii];
                cs = cs * sigf(gf + 1.0f) + sigf(gi) * tanhff(gj);
                cst[ch][ii] = cs;
                hp[ch][ii] = tanhff(cs) * sigf(go);
            }
        }

        __syncthreads();   // all GEMM reads of h(t-1) complete before overwrite

        // ---- write h(t) fp16 into A h-region ----
#pragma unroll
        for (int ch = 0; ch < 2; ++ch)
#pragma unroll
        for (int mt = 0; mt < 2; ++mt)
#pragma unroll
        for (int nt = 0; nt < 8; ++nt) {
            int r  = wm*32 + mt*16 + gid + ((tig & 1) << 3);
            int hu = ch*64 + wn*16 + nt*2 + (tig >> 1);
            Ast[r*AST + 32 + hu] = __float2half_rn(hp[ch][mt*8 + nt]);
        }
    }

    __syncthreads();

    // ---- FC: out = h @ W_fc + b_fc ----
    for (int idx = tid; idx < MTILE*LABELS; idx += NTHR) {
        int r = idx / LABELS, lab = idx - r*LABELS;
        float s = b_fc[lab];
#pragma unroll 4
        for (int k = 0; k < 128; ++k)
            s += __half2float(Ast[r*AST + 32 + k]) * W_fc[k*LABELS + lab];
        out[(size_t)(b0 + r)*LABELS + lab] = s;
    }
}

extern "C" void kernel_launch(void* const* d_in, const int* in_sizes, int n_in,
                              void* d_out, int out_size)
{
    const float* x      = (const float*)d_in[0];   // [32768, 28, 28]
    const float* W_lstm = (const float*)d_in[1];   // [156, 512]
    const float* b_lstm = (const float*)d_in[2];   // [512]
    const float* W_fc   = (const float*)d_in[3];   // [128, 10]
    const float* b_fc   = (const float*)d_in[4];   // [10]
    float* out          = (float*)d_out;           // [32768, 10]

    cudaFuncSetAttribute(lstm_mma, cudaFuncAttributeMaxDynamicSharedMemorySize, SMEM_TOTAL);
    lstm_mma<<<32768/MTILE, NTHR, SMEM_TOTAL>>>(x, W_lstm, b_lstm, W_fc, b_fc, out);
}

// round 10
// speedup vs baseline: 4.2731x; 1.5804x over previous
#include <cuda_runtime.h>
#include <cuda_fp16.h>
#include <cstdint>

#define T_STEPS 28
#define LABELS  10
#define MTILE   64
#define NTHR    512
#define AST     168                      // half stride (336B = odd multiple of 16B -> conflict-free ldmatrix)
#define SM_A    (512*AST)                // A starts after W' (in halfs)
#define SMEM_TOTAL ((512*AST + 64*AST)*2)   // 193536 B

__device__ __forceinline__ uint32_t smem_u32(const void* p){
    uint32_t a; asm("{ .reg .u64 t; cvta.to.shared.u64 t, %1; cvt.u32.u64 %0, t; }":"=r"(a):"l"(p)); return a;
}
__device__ __forceinline__ uint32_t h2u(__half2 v){ return *reinterpret_cast<uint32_t*>(&v); }

__device__ __forceinline__ float sigf(float x){ return 1.0f/(1.0f+__expf(-x)); }
__device__ __forceinline__ float tanhff(float x){ return 2.0f/(1.0f+__expf(-2.0f*x))-1.0f; }

#define LDSM4(r,a) asm volatile("ldmatrix.sync.aligned.m8n8.x4.shared.b16 {%0,%1,%2,%3},[%4];" \
    :"=r"((r)[0]),"=r"((r)[1]),"=r"((r)[2]),"=r"((r)[3]):"r"(a))
#define LDSM2(r,a) asm volatile("ldmatrix.sync.aligned.m8n8.x2.shared.b16 {%0,%1},[%2];" \
    :"=r"((r)[0]),"=r"((r)[1]):"r"(a))
#define MMA16816(c,a,b) asm volatile( \
    "mma.sync.aligned.m16n8k16.row.col.f32.f16.f16.f32 {%0,%1,%2,%3},{%4,%5,%6,%7},{%8,%9},{%0,%1,%2,%3};" \
    :"+f"((c)[0]),"+f"((c)[1]),"+f"((c)[2]),"+f"((c)[3]) \
    :"r"((a)[0]),"r"((a)[1]),"r"((a)[2]),"r"((a)[3]),"r"((b)[0]),"r"((b)[1]))

__global__ void __launch_bounds__(NTHR)
lstm_mma(const float* __restrict__ x, const float* __restrict__ W_lstm,
         const float* __restrict__ b_lstm, const float* __restrict__ W_fc,
         const float* __restrict__ b_fc, float* __restrict__ out)
{
    extern __shared__ __align__(16) __half sm[];
    __half* Wst = sm;            // [512 n'][AST k]  k-contiguous per column
    __half* Ast = sm + SM_A;     // [64 r][AST k]

    const int tid    = threadIdx.x;
    const int wid    = tid >> 5;
    const int lane   = tid & 31;
    const int wm     = wid & 1;           // 0..1 : rows 32*wm
    const int wslice = wid >> 1;          // 0..7 : 64 n'-cols per slice
    const int gid    = lane >> 2;
    const int tig    = lane & 3;
    const int b0     = blockIdx.x * MTILE;

    // ---- stage W' once: k-map {0..27:x-rows, 28:bias, 29..31:0, 32..159:h-rows},
    //      column interleave n' = 4*hu + g  (g: 0=i,1=j,2=f,3=o; orig col = g*128+hu) ----
    for (int idx = tid; idx < 512*160; idx += NTHR) {
        int k = idx >> 9, col = idx & 511;
        float v = 0.0f;
        if (k < 28)       v = W_lstm[k*512 + col];
        else if (k == 28) v = b_lstm[col];
        else if (k >= 32) v = W_lstm[(k-4)*512 + col];
        int np = ((col & 127) << 2) | (col >> 7);      // 4*hu + g
        Wst[np*AST + k] = __float2half_rn(v);
    }
    // ---- A static region: bias=1 at k=28, zeros k=29..159 (h starts zero) ----
    for (int idx = tid; idx < 64*132; idx += NTHR) {
        int r = idx / 132, k = 28 + idx % 132;
        Ast[r*AST + k] = __float2half_rn(k == 28 ? 1.0f : 0.0f);
    }

    const uint32_t abase = smem_u32(Ast);
    const uint32_t wbase = smem_u32(Wst);
    const uint32_t a_lane = (uint32_t)((lane & 15) * AST + (lane >> 4) * 8) * 2;
    const uint32_t b_lane = (uint32_t)((lane & 7) * AST + ((lane >> 3) & 1) * 8) * 2;

    float cst[16], hp[16];
#pragma unroll
    for (int i = 0; i < 16; ++i) cst[i] = 0.f;

    const bool odd = (tig & 1);

    for (int t = 0; t < T_STEPS; ++t) {
        // ---- stage x_t fp16 into A cols 0..27 ----
        {
            int idx = tid;
            if (idx < 64*7) {
                int r = idx / 7, q = idx - r*7;
                float4 v = *(const float4*)(x + (size_t)(b0 + r)*784 + t*28 + q*4);
                uint2 pk;
                pk.x = h2u(__floats2half2_rn(v.x, v.y));
                pk.y = h2u(__floats2half2_rn(v.z, v.w));
                *(uint2*)(Ast + r*AST + 4*q) = pk;
            }
        }
        __syncthreads();   // x + h(t-1) + W' visible to all

#pragma unroll
        for (int ch = 0; ch < 2; ++ch) {
            float acc[2][4][4];
#pragma unroll
            for (int nt = 0; nt < 4; ++nt)
#pragma unroll
                for (int e = 0; e < 4; ++e) { acc[0][nt][e] = 0.f; acc[1][nt][e] = 0.f; }

            // ---- GEMM: rows 32wm..+31, cols n' = wslice*64 + ch*32 .. +31, K=160 ----
#pragma unroll
            for (int kt = 0; kt < 10; ++kt) {
                uint32_t a0[4], a1[4];
                uint32_t aaddr = abase + (uint32_t)(wm*32*AST + kt*16)*2 + a_lane;
                LDSM4(a0, aaddr);
                LDSM4(a1, aaddr + 16*AST*2);
#pragma unroll
                for (int nt = 0; nt < 4; ++nt) {
                    uint32_t b[2];
                    uint32_t baddr = wbase + (uint32_t)(((wslice*64 + ch*32 + nt*8)*AST) + kt*16)*2 + b_lane;
                    LDSM2(b, baddr);
                    MMA16816(acc[0][nt], a0, b);
                    MMA16816(acc[1][nt], a1, b);
                }
            }

            // ---- epilogue: lane-pair exchange -> uniform cell update ----
#pragma unroll
            for (int mt = 0; mt < 2; ++mt)
#pragma unroll
            for (int nt = 0; nt < 4; ++nt) {
                float c0 = acc[mt][nt][0], c1 = acc[mt][nt][1];
                float c2 = acc[mt][nt][2], c3 = acc[mt][nt][3];
                float s0 = odd ? c0 : c2;
                float s1 = odd ? c1 : c3;
                float r0 = __shfl_sync(0xffffffffu, s0, lane ^ 1);
                float r1 = __shfl_sync(0xffffffffu, s1, lane ^ 1);
                float gi = odd ? r0 : c0;
                float gj = odd ? r1 : c1;
                float gf = odd ? c2 : r0;
                float go = odd ? c3 : r1;
                int ii = ch*8 + mt*4 + nt;
                float cs = cst[ii];
                cs = cs * sigf(gf + 1.0f) + sigf(gi) * tanhff(gj);
                cst[ii] = cs;
                hp[ii] = tanhff(cs) * sigf(go);
            }
        }

        __syncthreads();   // all GEMM reads of h(t-1) complete before overwrite

        // ---- write h(t) fp16 into A h-region ----
#pragma unroll
        for (int ch = 0; ch < 2; ++ch)
#pragma unroll
        for (int mt = 0; mt < 2; ++mt)
#pragma unroll
        for (int nt = 0; nt < 4; ++nt) {
            int r  = wm*32 + mt*16 + gid + ((tig & 1) << 3);
            int hu = wslice*16 + ch*8 + nt*2 + (tig >> 1);
            Ast[r*AST + 32 + hu] = __float2half_rn(hp[ch*8 + mt*4 + nt]);
        }
    }

    __syncthreads();

    // ---- FC: out = h @ W_fc + b_fc ----
    for (int idx = tid; idx < MTILE*LABELS; idx += NTHR) {
        int r = idx / LABELS, lab = idx - r*LABELS;
        float s = b_fc[lab];
#pragma unroll 4
        for (int k = 0; k < 128; ++k)
            s += __half2float(Ast[r*AST + 32 + k]) * W_fc[k*LABELS + lab];
        out[(size_t)(b0 + r)*LABELS + lab] = s;
    }
}

extern "C" void kernel_launch(void* const* d_in, const int* in_sizes, int n_in,
                              void* d_out, int out_size)
{
    const float* x      = (const float*)d_in[0];   // [32768, 28, 28]
    const float* W_lstm = (const float*)d_in[1];   // [156, 512]
    const float* b_lstm = (const float*)d_in[2];   // [512]
    const float* W_fc   = (const float*)d_in[3];   // [128, 10]
    const float* b_fc   = (const float*)d_in[4];   // [10]
    float* out          = (float*)d_out;           // [32768, 10]

    cudaFuncSetAttribute(lstm_mma, cudaFuncAttributeMaxDynamicSharedMemorySize, SMEM_TOTAL);
    lstm_mma<<<32768/MTILE, NTHR, SMEM_TOTAL>>>(x, W_lstm, b_lstm, W_fc, b_fc, out);
}